// round 2
// baseline (speedup 1.0000x reference)
#include <cuda_runtime.h>
#include <math.h>

#define NN 25000
#define NE 400000
#define ND 100
#define EDICT 16

#define TPB 256
#define NPB 32                      // nodes per GEMM block
#define NODE_BLKS 782               // ceil(25000/32)
#define RATIO 5
#define TOTAL_BLKS (NODE_BLKS * RATIO)        // 3910
#define EDGE_BLKS (TOTAL_BLKS - NODE_BLKS)    // 3128
#define EVEC (NE * 32)              // 12,800,000 float4 slots in edge output
#define CHUNK ((EVEC + EDGE_BLKS - 1) / EDGE_BLKS)  // 4093

// ---------------- device scratch ----------------
__device__ float4 g_tabT[ND * 32];        // P table: [d][f] -> 4 heads
__device__ float4 g_s1[ND];
__device__ float4 g_s2[ND];
__device__ float4 g_s3[EDICT];
__device__ float4 g_lnedge[EDICT * 32];   // 16 LN'd edge rows
__device__ float4 g_segsum[NN];
__device__ int    g_deg[NN];
__device__ float4 g_Wmat[NN * ND];        // [t][d] -> per-head sum of exp (40MB)

// ---------------- zero scratch ----------------
__global__ void k_zero() {
    int i = blockIdx.x * blockDim.x + threadIdx.x;
    float4 z = make_float4(0.f, 0.f, 0.f, 0.f);
    if (i < NN * ND) g_Wmat[i] = z;
    if (i < NN) { g_segsum[i] = z; g_deg[i] = 0; }
}

// ---------------- build tables ----------------
__global__ void k_tables(const float* __restrict__ node_emb,
                         const float* __restrict__ edge_emb,
                         const float* __restrict__ W_t, const float* __restrict__ b_t,
                         const float* __restrict__ W_e, const float* __restrict__ b_e,
                         const float* __restrict__ a_w,
                         const float* __restrict__ gamma, const float* __restrict__ beta) {
    __shared__ float sh[128];
    __shared__ float red[8];
    int b = blockIdx.x;
    int tid = threadIdx.x;
    bool isnode = (b < ND);
    const float* emb  = isnode ? (node_emb + b * 128) : (edge_emb + (b - ND) * 128);
    const float* W    = isnode ? W_t : W_e;
    const float* bias = isnode ? b_t : b_e;

    sh[tid] = emb[tid];
    __syncthreads();

    float acc = bias[tid];
#pragma unroll 8
    for (int i = 0; i < 128; i++) acc += sh[i] * W[i * 128 + tid];

    int h = tid >> 5;
    int f = tid & 31;

    if (isnode) {
        ((float*)&g_tabT[b * 32 + f])[h] = acc;
        float u = acc * a_w[f];
        float v = acc * a_w[32 + f];
#pragma unroll
        for (int o = 16; o; o >>= 1) {
            u += __shfl_xor_sync(0xFFFFFFFFu, u, o);
            v += __shfl_xor_sync(0xFFFFFFFFu, v, o);
        }
        if (f == 0) {
            ((float*)&g_s1[b])[h] = u;
            ((float*)&g_s2[b])[h] = v;
        }
    } else {
        int k = b - ND;
        float u = acc * a_w[64 + f];
#pragma unroll
        for (int o = 16; o; o >>= 1) u += __shfl_xor_sync(0xFFFFFFFFu, u, o);
        if (f == 0) ((float*)&g_s3[k])[h] = u;

        float s = acc;
#pragma unroll
        for (int o = 16; o; o >>= 1) s += __shfl_xor_sync(0xFFFFFFFFu, s, o);
        if (f == 0) red[h] = s;
        __syncthreads();
        float mu = (red[0] + red[1] + red[2] + red[3]) * (1.f / 128.f);
        float dd = acc - mu;
        float sq = dd * dd;
#pragma unroll
        for (int o = 16; o; o >>= 1) sq += __shfl_xor_sync(0xFFFFFFFFu, sq, o);
        if (f == 0) red[4 + h] = sq;
        __syncthreads();
        float var = (red[4] + red[5] + red[6] + red[7]) * (1.f / 128.f);
        float val = dd * rsqrtf(var + 1e-5f) * gamma[tid] + beta[tid];
        ((float*)g_lnedge)[k * 128 + tid] = val;
    }
}

// ---------------- per-edge pass: exp(logit) accumulation ----------------
__global__ void k_edges(const int* __restrict__ nf, const int* __restrict__ ef,
                        const int* __restrict__ ei, const float* __restrict__ a_b) {
    int e = blockIdx.x * blockDim.x + threadIdx.x;
    if (e >= NE) return;
    int s = ei[e];
    int t = ei[NE + e];
    int k = ef[e];
    int ds = nf[s];
    int dt = nf[t];
    float ab = *a_b;
    float4 z1 = g_s1[dt];
    float4 z2 = g_s2[ds];
    float4 z3 = g_s3[k];

    float zx = z1.x + z2.x + z3.x + ab;
    float zy = z1.y + z2.y + z3.y + ab;
    float zz = z1.z + z2.z + z3.z + ab;
    float zw = z1.w + z2.w + z3.w + ab;
    zx = zx >= 0.f ? zx : 0.2f * zx;
    zy = zy >= 0.f ? zy : 0.2f * zy;
    zz = zz >= 0.f ? zz : 0.2f * zz;
    zw = zw >= 0.f ? zw : 0.2f * zw;
    float ex = __expf(zx), ey = __expf(zy), ez = __expf(zz), ew = __expf(zw);

    float4* wp = &g_Wmat[t * ND + ds];
    asm volatile("red.global.add.v4.f32 [%0], {%1,%2,%3,%4};"
                 :: "l"(wp), "f"(ex), "f"(ey), "f"(ez), "f"(ew) : "memory");
    float4* sp = &g_segsum[t];
    asm volatile("red.global.add.v4.f32 [%0], {%1,%2,%3,%4};"
                 :: "l"(sp), "f"(ex), "f"(ey), "f"(ez), "f"(ew) : "memory");
    atomicAdd(&g_deg[t], 1);
}

// ---------------- fused: node GEMM+LN blocks interleaved with edge-out blocks ----------------
__global__ void __launch_bounds__(TPB) k_main(
    const int* __restrict__ nf, const int* __restrict__ ef,
    const float* __restrict__ gamma, const float* __restrict__ beta,
    float* __restrict__ out_node, float4* __restrict__ out_edge)
{
    int bid = blockIdx.x;

    if (bid % RATIO != 0) {
        // ---- edge output block: streaming broadcast-gather write ----
        int eb = bid - bid / RATIO - 1;          // 0..EDGE_BLKS-1
        int start = eb * CHUNK;
        int end = start + CHUNK;
        if (end > EVEC) end = EVEC;
        for (int i = start + (int)threadIdx.x; i < end; i += TPB) {
            int e = i >> 5;
            int c = i & 31;
            out_edge[i] = g_lnedge[(ef[e] << 5) + c];
        }
        return;
    }

    // ---- node GEMM block: 32 nodes, K=100, N=128 ----
    extern __shared__ float4 sm[];
    float4* Ps = sm;            // [100][32] : 51.2KB
    float4* Ws = sm + ND * 32;  // [32][100] : 51.2KB
    int nb = bid / RATIO;
    int base = nb * NPB;
    int tid = threadIdx.x;

    for (int i = tid; i < ND * 32; i += TPB) Ps[i] = g_tabT[i];
    for (int i = tid; i < NPB * ND; i += TPB) {
        int t = base + i / ND;
        Ws[i] = (t < NN) ? g_Wmat[t * ND + (i % ND)] : make_float4(0.f, 0.f, 0.f, 0.f);
    }
    __syncthreads();

    int w = tid >> 5, l = tid & 31;
    const float4* W0 = &Ws[(4 * w + 0) * ND];
    const float4* W1 = &Ws[(4 * w + 1) * ND];
    const float4* W2 = &Ws[(4 * w + 2) * ND];
    const float4* W3 = &Ws[(4 * w + 3) * ND];

    float4 acc[4];
#pragma unroll
    for (int n = 0; n < 4; n++) acc[n] = make_float4(0.f, 0.f, 0.f, 0.f);

#pragma unroll 2
    for (int d = 0; d < ND; d++) {
        float4 w0 = W0[d], w1 = W1[d], w2 = W2[d], w3 = W3[d];
        // exp-sums are >= 0; x-component nonzero iff any edge contributed
        if (w0.x + w1.x + w2.x + w3.x > 0.f) {
            float4 p = Ps[(d << 5) + l];
            acc[0].x += w0.x * p.x; acc[0].y += w0.y * p.y; acc[0].z += w0.z * p.z; acc[0].w += w0.w * p.w;
            acc[1].x += w1.x * p.x; acc[1].y += w1.y * p.y; acc[1].z += w1.z * p.z; acc[1].w += w1.w * p.w;
            acc[2].x += w2.x * p.x; acc[2].y += w2.y * p.y; acc[2].z += w2.z * p.z; acc[2].w += w2.w * p.w;
            acc[3].x += w3.x * p.x; acc[3].y += w3.y * p.y; acc[3].z += w3.z * p.z; acc[3].w += w3.w * p.w;
        }
    }

    float gl0 = gamma[l],      bl0 = beta[l];
    float gl1 = gamma[32 + l], bl1 = beta[32 + l];
    float gl2 = gamma[64 + l], bl2 = beta[64 + l];
    float gl3 = gamma[96 + l], bl3 = beta[96 + l];

#pragma unroll
    for (int n = 0; n < 4; n++) {
        int t = base + 4 * w + n;
        if (t >= NN) break;
        float4 ss = g_segsum[t];
        float r0 = ss.x > 0.f ? 1.f / ss.x : 0.f;
        float r1 = ss.y > 0.f ? 1.f / ss.y : 0.f;
        float r2 = ss.z > 0.f ? 1.f / ss.z : 0.f;
        float r3 = ss.w > 0.f ? 1.f / ss.w : 0.f;
        float dg = (float)g_deg[t];
        float4 p = Ps[(nf[t] << 5) + l];

        float v0 = acc[n].x * r0 + dg * p.x;
        float v1 = acc[n].y * r1 + dg * p.y;
        float v2 = acc[n].z * r2 + dg * p.z;
        float v3 = acc[n].w * r3 + dg * p.w;

        float s = v0 + v1 + v2 + v3;
#pragma unroll
        for (int o = 16; o; o >>= 1) s += __shfl_xor_sync(0xFFFFFFFFu, s, o);
        float mu = s * (1.f / 128.f);
        float d0 = v0 - mu, d1 = v1 - mu, d2 = v2 - mu, d3 = v3 - mu;
        float sq = d0 * d0 + d1 * d1 + d2 * d2 + d3 * d3;
#pragma unroll
        for (int o = 16; o; o >>= 1) sq += __shfl_xor_sync(0xFFFFFFFFu, sq, o);
        float rs = rsqrtf(sq * (1.f / 128.f) + 1e-5f);

        float* o0 = out_node + (size_t)t * 128;
        o0[l]      = d0 * rs * gl0 + bl0;
        o0[32 + l] = d1 * rs * gl1 + bl1;
        o0[64 + l] = d2 * rs * gl2 + bl2;
        o0[96 + l] = d3 * rs * gl3 + bl3;
    }
}

// ---------------- launch ----------------
extern "C" void kernel_launch(void* const* d_in, const int* in_sizes, int n_in,
                              void* d_out, int out_size) {
    const int*   nf       = (const int*)d_in[0];
    const int*   ef       = (const int*)d_in[1];
    const int*   ei       = (const int*)d_in[2];
    const float* node_emb = (const float*)d_in[3];
    const float* edge_emb = (const float*)d_in[4];
    const float* W_t      = (const float*)d_in[5];
    const float* b_t      = (const float*)d_in[6];
    const float* W_e      = (const float*)d_in[7];
    const float* b_e      = (const float*)d_in[8];
    const float* a_w      = (const float*)d_in[9];
    const float* a_b      = (const float*)d_in[10];
    const float* gamma    = (const float*)d_in[11];
    const float* beta     = (const float*)d_in[12];

    float* out_node = (float*)d_out;                                  // [25000,128]
    float4* out_edge = (float4*)((float*)d_out + (size_t)NN * 128);   // [400000,128]

    k_zero<<<(NN * ND + 255) / 256, 256>>>();
    k_tables<<<ND + EDICT, 128>>>(node_emb, edge_emb, W_t, b_t, W_e, b_e, a_w, gamma, beta);
    k_edges<<<(NE + 255) / 256, 256>>>(nf, ef, ei, a_b);

    cudaFuncSetAttribute(k_main, cudaFuncAttributeMaxDynamicSharedMemorySize,
                         (ND * 32 + NPB * ND) * sizeof(float4));
    k_main<<<TOTAL_BLKS, TPB, (ND * 32 + NPB * ND) * sizeof(float4)>>>(
        nf, ef, gamma, beta, out_node, out_edge);
}

// round 3
// speedup vs baseline: 1.4766x; 1.4766x over previous
#include <cuda_runtime.h>
#include <math.h>

#define NN 25000
#define NE 400000
#define ND 100
#define EDICT 16

// ---------------- device scratch ----------------
__device__ float4 g_tabT[ND * 32];        // P table: [d][f] -> 4 heads (51.2KB)
__device__ float4 g_s1[ND];
__device__ float4 g_s2[ND];
__device__ float4 g_s3[EDICT];
__device__ float4 g_lnedge[EDICT * 32];   // 16 LN'd edge rows (8KB)
__device__ float4 g_segsum[NN];
__device__ int    g_deg[NN];
__device__ float4 g_Wmat[NN * ND];        // [t][d] -> per-head sum of exp (40MB)

// ==================== K1: fused tables + zero ====================
#define TAB_BLKS (ND + EDICT)                  // 116
#define ZERO_ELT (NN * ND)                     // 2,500,000 float4
#define ZERO_BLKS ((ZERO_ELT + 255) / 256)     // 9766

__global__ void __launch_bounds__(256) k1_init(
    const float* __restrict__ node_emb, const float* __restrict__ edge_emb,
    const float* __restrict__ W_t, const float* __restrict__ b_t,
    const float* __restrict__ W_e, const float* __restrict__ b_e,
    const float* __restrict__ a_w,
    const float* __restrict__ gamma, const float* __restrict__ beta)
{
    int bid = blockIdx.x;
    int tid = threadIdx.x;

    if (bid >= TAB_BLKS) {
        // ---- zero blocks ----
        int i = (bid - TAB_BLKS) * 256 + tid;
        float4 z = make_float4(0.f, 0.f, 0.f, 0.f);
        if (i < ZERO_ELT) g_Wmat[i] = z;
        if (i < NN) { g_segsum[i] = z; g_deg[i] = 0; }
        return;
    }

    // ---- table block: one dict row, threads 0..127 active, all 256 sync ----
    __shared__ float sh[128];
    __shared__ float red[8];
    bool act = tid < 128;
    bool isnode = (bid < ND);
    const float* emb  = isnode ? (node_emb + bid * 128) : (edge_emb + (bid - ND) * 128);
    const float* W    = isnode ? W_t : W_e;
    const float* bias = isnode ? b_t : b_e;

    if (act) sh[tid] = emb[tid];
    __syncthreads();

    float acc = 0.f;
    if (act) {
        acc = bias[tid];
#pragma unroll 8
        for (int i = 0; i < 128; i++) acc += sh[i] * W[i * 128 + tid];
    }

    int h = tid >> 5;
    int f = tid & 31;

    if (isnode) {
        if (act) {
            ((float*)&g_tabT[bid * 32 + f])[h] = acc;
            float u = acc * a_w[f];
            float v = acc * a_w[32 + f];
#pragma unroll
            for (int o = 16; o; o >>= 1) {
                u += __shfl_xor_sync(0xFFFFFFFFu, u, o);
                v += __shfl_xor_sync(0xFFFFFFFFu, v, o);
            }
            if (f == 0) {
                ((float*)&g_s1[bid])[h] = u;
                ((float*)&g_s2[bid])[h] = v;
            }
        }
    } else {
        int k = bid - ND;
        float s = 0.f, u = 0.f;
        if (act) {
            u = acc * a_w[64 + f];
            s = acc;
        }
#pragma unroll
        for (int o = 16; o; o >>= 1) {
            u += __shfl_xor_sync(0xFFFFFFFFu, u, o);
            s += __shfl_xor_sync(0xFFFFFFFFu, s, o);
        }
        if (act && f == 0) {
            ((float*)&g_s3[k])[h] = u;
            red[h] = s;
        }
        __syncthreads();
        float mu = (red[0] + red[1] + red[2] + red[3]) * (1.f / 128.f);
        float dd = act ? (acc - mu) : 0.f;
        float sq = dd * dd;
#pragma unroll
        for (int o = 16; o; o >>= 1) sq += __shfl_xor_sync(0xFFFFFFFFu, sq, o);
        if (act && f == 0) red[4 + h] = sq;
        __syncthreads();
        if (act) {
            float var = (red[4] + red[5] + red[6] + red[7]) * (1.f / 128.f);
            float val = dd * rsqrtf(var + 1e-5f) * gamma[tid] + beta[tid];
            ((float*)g_lnedge)[k * 128 + tid] = val;
        }
    }
}

// ==================== K2: edge atomics + edge-out part A ====================
// Edge-out half A covers edges [0, NE/2). Role by bid%5: <2 -> eout, else edges.
#define K2_TOT 2605                 // 1042 eout blocks + 1563 edge blocks
#define EO_A_BLKS 1042
#define EO_SPLIT (NE / 2)           // 200000

__global__ void __launch_bounds__(256) k2_edges(
    const int* __restrict__ nf, const int* __restrict__ ef,
    const int* __restrict__ ei, const float* __restrict__ a_b,
    float4* __restrict__ out_edge)
{
    int bid = blockIdx.x;
    int tid = threadIdx.x;
    int m = bid % 5;

    if (m < 2) {
        // ---- edge-out streaming: one warp per edge, grid-stride ----
        int eb = (bid / 5) * 2 + m;                  // 0..EO_A_BLKS-1
        int l = tid & 31;
        int gw = eb * 8 + (tid >> 5);                // global warp
        for (int e = gw; e < EO_SPLIT; e += EO_A_BLKS * 8) {
            int k = ef[e];
            out_edge[(size_t)e * 32 + l] = g_lnedge[(k << 5) + l];
        }
        return;
    }

    // ---- edge logit pass ----
    int eb = (bid / 5) * 3 + (m - 2);
    int e = eb * 256 + tid;
    if (e >= NE) return;
    int s = ei[e];
    int t = ei[NE + e];
    int k = ef[e];
    int ds = nf[s];
    int dt = nf[t];
    float ab = *a_b;
    float4 z1 = g_s1[dt];
    float4 z2 = g_s2[ds];
    float4 z3 = g_s3[k];

    float zx = z1.x + z2.x + z3.x + ab;
    float zy = z1.y + z2.y + z3.y + ab;
    float zz = z1.z + z2.z + z3.z + ab;
    float zw = z1.w + z2.w + z3.w + ab;
    zx = zx >= 0.f ? zx : 0.2f * zx;
    zy = zy >= 0.f ? zy : 0.2f * zy;
    zz = zz >= 0.f ? zz : 0.2f * zz;
    zw = zw >= 0.f ? zw : 0.2f * zw;
    float ex = __expf(zx), ey = __expf(zy), ez = __expf(zz), ew = __expf(zw);

    float4* wp = &g_Wmat[t * ND + ds];
    asm volatile("red.global.add.v4.f32 [%0], {%1,%2,%3,%4};"
                 :: "l"(wp), "f"(ex), "f"(ey), "f"(ez), "f"(ew) : "memory");
    float4* sp = &g_segsum[t];
    asm volatile("red.global.add.v4.f32 [%0], {%1,%2,%3,%4};"
                 :: "l"(sp), "f"(ex), "f"(ey), "f"(ez), "f"(ew) : "memory");
    atomicAdd(&g_deg[t], 1);
}

// ==================== K3: node GEMM+LN + edge-out part B ====================
#define NPB3 16                     // nodes per GEMM block
#define NODE_BLKS3 ((NN + NPB3 - 1) / NPB3)   // 1563
#define K3_TOT 2605                 // 1042 eout + 1563 node
#define EO_B_BLKS 1042
#define SMEM3 (NPB3 * ND * sizeof(float4))    // 25.6KB

__global__ void __launch_bounds__(256) k3_nodes(
    const int* __restrict__ nf, const int* __restrict__ ef,
    const float* __restrict__ gamma, const float* __restrict__ beta,
    float* __restrict__ out_node, float4* __restrict__ out_edge)
{
    int bid = blockIdx.x;
    int tid = threadIdx.x;
    int m = bid % 5;

    if (m < 2) {
        // ---- edge-out streaming: edges [EO_SPLIT, NE) ----
        int eb = (bid / 5) * 2 + m;
        int l = tid & 31;
        int gw = eb * 8 + (tid >> 5);
        for (int e = EO_SPLIT + gw; e < NE; e += EO_B_BLKS * 8) {
            int k = ef[e];
            out_edge[(size_t)e * 32 + l] = g_lnedge[(k << 5) + l];
        }
        return;
    }

    // ---- node GEMM block: 16 nodes, K=100 ----
    extern __shared__ float4 Ws[];   // [16][100]
    int nb = (bid / 5) * 3 + (m - 2);
    if (nb >= NODE_BLKS3) return;
    int base = nb * NPB3;

    for (int i = tid; i < NPB3 * ND; i += 256) {
        int t = base + i / ND;
        Ws[i] = (t < NN) ? g_Wmat[t * ND + (i % ND)] : make_float4(0.f, 0.f, 0.f, 0.f);
    }
    __syncthreads();

    int w = tid >> 5, l = tid & 31;
    const float4* Wa = &Ws[(2 * w + 0) * ND];
    const float4* Wb = &Ws[(2 * w + 1) * ND];

    float4 acc0 = make_float4(0.f, 0.f, 0.f, 0.f);
    float4 acc1 = make_float4(0.f, 0.f, 0.f, 0.f);

#pragma unroll 4
    for (int d = 0; d < ND; d++) {
        float4 wa = Wa[d], wb = Wb[d];
        if (wa.x + wb.x > 0.f) {               // exp-sums strictly positive when present
            float4 p = __ldg(&g_tabT[(d << 5) + l]);
            acc0.x += wa.x * p.x; acc0.y += wa.y * p.y; acc0.z += wa.z * p.z; acc0.w += wa.w * p.w;
            acc1.x += wb.x * p.x; acc1.y += wb.y * p.y; acc1.z += wb.z * p.z; acc1.w += wb.w * p.w;
        }
    }

    float gl0 = gamma[l],      bl0 = beta[l];
    float gl1 = gamma[32 + l], bl1 = beta[32 + l];
    float gl2 = gamma[64 + l], bl2 = beta[64 + l];
    float gl3 = gamma[96 + l], bl3 = beta[96 + l];

#pragma unroll
    for (int n = 0; n < 2; n++) {
        int t = base + 2 * w + n;
        if (t >= NN) break;
        float4 a = (n == 0) ? acc0 : acc1;
        float4 ss = g_segsum[t];
        float r0 = ss.x > 0.f ? 1.f / ss.x : 0.f;
        float r1 = ss.y > 0.f ? 1.f / ss.y : 0.f;
        float r2 = ss.z > 0.f ? 1.f / ss.z : 0.f;
        float r3 = ss.w > 0.f ? 1.f / ss.w : 0.f;
        float dg = (float)g_deg[t];
        float4 p = __ldg(&g_tabT[(nf[t] << 5) + l]);

        float v0 = a.x * r0 + dg * p.x;
        float v1 = a.y * r1 + dg * p.y;
        float v2 = a.z * r2 + dg * p.z;
        float v3 = a.w * r3 + dg * p.w;

        float s = v0 + v1 + v2 + v3;
#pragma unroll
        for (int o = 16; o; o >>= 1) s += __shfl_xor_sync(0xFFFFFFFFu, s, o);
        float mu = s * (1.f / 128.f);
        float d0 = v0 - mu, d1 = v1 - mu, d2 = v2 - mu, d3 = v3 - mu;
        float sq = d0 * d0 + d1 * d1 + d2 * d2 + d3 * d3;
#pragma unroll
        for (int o = 16; o; o >>= 1) sq += __shfl_xor_sync(0xFFFFFFFFu, sq, o);
        float rs = rsqrtf(sq * (1.f / 128.f) + 1e-5f);

        float* o0 = out_node + (size_t)t * 128;
        o0[l]      = d0 * rs * gl0 + bl0;
        o0[32 + l] = d1 * rs * gl1 + bl1;
        o0[64 + l] = d2 * rs * gl2 + bl2;
        o0[96 + l] = d3 * rs * gl3 + bl3;
    }
}

// ==================== launch ====================
extern "C" void kernel_launch(void* const* d_in, const int* in_sizes, int n_in,
                              void* d_out, int out_size) {
    const int*   nf       = (const int*)d_in[0];
    const int*   ef       = (const int*)d_in[1];
    const int*   ei       = (const int*)d_in[2];
    const float* node_emb = (const float*)d_in[3];
    const float* edge_emb = (const float*)d_in[4];
    const float* W_t      = (const float*)d_in[5];
    const float* b_t      = (const float*)d_in[6];
    const float* W_e      = (const float*)d_in[7];
    const float* b_e      = (const float*)d_in[8];
    const float* a_w      = (const float*)d_in[9];
    const float* a_b      = (const float*)d_in[10];
    const float* gamma    = (const float*)d_in[11];
    const float* beta     = (const float*)d_in[12];

    float* out_node = (float*)d_out;                                  // [25000,128]
    float4* out_edge = (float4*)((float*)d_out + (size_t)NN * 128);   // [400000,128]

    k1_init<<<TAB_BLKS + ZERO_BLKS, 256>>>(node_emb, edge_emb, W_t, b_t,
                                           W_e, b_e, a_w, gamma, beta);
    k2_edges<<<K2_TOT, 256>>>(nf, ef, ei, a_b, out_edge);
    k3_nodes<<<K3_TOT, 256, SMEM3>>>(nf, ef, gamma, beta, out_node, out_edge);
}

// round 4
// speedup vs baseline: 1.6050x; 1.0870x over previous
#include <cuda_runtime.h>
#include <math.h>

#define NN 25000
#define NE 400000
#define ND 100
#define EDICT 16

// ---------------- device scratch ----------------
__device__ float4 g_tabT[ND * 32];        // P table: [d][f] -> 4 heads (51.2KB)
__device__ float4 g_s1[ND];
__device__ float4 g_s2[ND];
__device__ float4 g_s3[EDICT];
__device__ float4 g_lnedge[EDICT * 32];   // 16 LN'd edge rows (8KB)
__device__ int    g_deg[NN];
__device__ float4 g_Wmat[NN * ND];        // [t][d] -> per-head sum of exp (40MB)

// ==================== K1: tables only (zeroing is a memset node) ====================
__global__ void __launch_bounds__(128) k1_tables(
    const float* __restrict__ node_emb, const float* __restrict__ edge_emb,
    const float* __restrict__ W_t, const float* __restrict__ b_t,
    const float* __restrict__ W_e, const float* __restrict__ b_e,
    const float* __restrict__ a_w,
    const float* __restrict__ gamma, const float* __restrict__ beta)
{
    __shared__ float sh[128];
    __shared__ float red[8];
    int b = blockIdx.x;
    int tid = threadIdx.x;
    bool isnode = (b < ND);
    const float* emb  = isnode ? (node_emb + b * 128) : (edge_emb + (b - ND) * 128);
    const float* W    = isnode ? W_t : W_e;
    const float* bias = isnode ? b_t : b_e;

    sh[tid] = emb[tid];
    __syncthreads();

    float acc = bias[tid];
#pragma unroll 8
    for (int i = 0; i < 128; i++) acc += sh[i] * W[i * 128 + tid];

    int h = tid >> 5;
    int f = tid & 31;

    if (isnode) {
        ((float*)&g_tabT[b * 32 + f])[h] = acc;
        float u = acc * a_w[f];
        float v = acc * a_w[32 + f];
#pragma unroll
        for (int o = 16; o; o >>= 1) {
            u += __shfl_xor_sync(0xFFFFFFFFu, u, o);
            v += __shfl_xor_sync(0xFFFFFFFFu, v, o);
        }
        if (f == 0) {
            ((float*)&g_s1[b])[h] = u;
            ((float*)&g_s2[b])[h] = v;
        }
    } else {
        int k = b - ND;
        float u = acc * a_w[64 + f];
        float s = acc;
#pragma unroll
        for (int o = 16; o; o >>= 1) {
            u += __shfl_xor_sync(0xFFFFFFFFu, u, o);
            s += __shfl_xor_sync(0xFFFFFFFFu, s, o);
        }
        if (f == 0) {
            ((float*)&g_s3[k])[h] = u;
            red[h] = s;
        }
        __syncthreads();
        float mu = (red[0] + red[1] + red[2] + red[3]) * (1.f / 128.f);
        float dd = acc - mu;
        float sq = dd * dd;
#pragma unroll
        for (int o = 16; o; o >>= 1) sq += __shfl_xor_sync(0xFFFFFFFFu, sq, o);
        if (f == 0) red[4 + h] = sq;
        __syncthreads();
        float var = (red[4] + red[5] + red[6] + red[7]) * (1.f / 128.f);
        float val = dd * rsqrtf(var + 1e-5f) * gamma[tid] + beta[tid];
        ((float*)g_lnedge)[k * 128 + tid] = val;
    }
}

// ==================== K2: edge atomics + edge-out part A ====================
#define K2_TOT 2605                 // 1042 eout + 1563 edge blocks (mod-5 interleave)
#define EO_A_BLKS 1042
#define EO_SPLIT (NE / 2)           // 200000

__global__ void __launch_bounds__(256) k2_edges(
    const int* __restrict__ nf, const int* __restrict__ ef,
    const int* __restrict__ ei, const float* __restrict__ a_b,
    float4* __restrict__ out_edge)
{
    int bid = blockIdx.x;
    int tid = threadIdx.x;
    int m = bid % 5;

    if (m < 2) {
        // ---- edge-out streaming (evict-first stores) ----
        int eb = (bid / 5) * 2 + m;
        int l = tid & 31;
        int gw = eb * 8 + (tid >> 5);
        for (int e = gw; e < EO_SPLIT; e += EO_A_BLKS * 8) {
            int k = ef[e];
            float4 v = g_lnedge[(k << 5) + l];
            __stcs(&out_edge[(size_t)e * 32 + l], v);
        }
        return;
    }

    // ---- edge logit pass ----
    int eb = (bid / 5) * 3 + (m - 2);
    int e = eb * 256 + tid;
    if (e >= NE) return;
    int s = ei[e];
    int t = ei[NE + e];
    int k = ef[e];
    int ds = nf[s];
    int dt = nf[t];
    float ab = *a_b;
    float4 z1 = g_s1[dt];
    float4 z2 = g_s2[ds];
    float4 z3 = g_s3[k];

    float zx = z1.x + z2.x + z3.x + ab;
    float zy = z1.y + z2.y + z3.y + ab;
    float zz = z1.z + z2.z + z3.z + ab;
    float zw = z1.w + z2.w + z3.w + ab;
    zx = zx >= 0.f ? zx : 0.2f * zx;
    zy = zy >= 0.f ? zy : 0.2f * zy;
    zz = zz >= 0.f ? zz : 0.2f * zz;
    zw = zw >= 0.f ? zw : 0.2f * zw;
    float ex = __expf(zx), ey = __expf(zy), ez = __expf(zz), ew = __expf(zw);

    float4* wp = &g_Wmat[t * ND + ds];
    asm volatile("red.global.add.v4.f32 [%0], {%1,%2,%3,%4};"
                 :: "l"(wp), "f"(ex), "f"(ey), "f"(ez), "f"(ew) : "memory");
    atomicAdd(&g_deg[t], 1);
}

// ==================== K3: node GEMM+LN (segsum derived in-loop) + edge-out B ====================
#define NPB3 16
#define NODE_BLKS3 ((NN + NPB3 - 1) / NPB3)   // 1563
#define K3_TOT 2605
#define EO_B_BLKS 1042
#define SMEM3 (NPB3 * ND * sizeof(float4))    // 25.6KB

__global__ void __launch_bounds__(256) k3_nodes(
    const int* __restrict__ nf, const int* __restrict__ ef,
    const float* __restrict__ gamma, const float* __restrict__ beta,
    float* __restrict__ out_node, float4* __restrict__ out_edge)
{
    int bid = blockIdx.x;
    int tid = threadIdx.x;
    int m = bid % 5;

    if (m < 2) {
        // ---- edge-out streaming: edges [EO_SPLIT, NE) ----
        int eb = (bid / 5) * 2 + m;
        int l = tid & 31;
        int gw = eb * 8 + (tid >> 5);
        for (int e = EO_SPLIT + gw; e < NE; e += EO_B_BLKS * 8) {
            int k = ef[e];
            float4 v = g_lnedge[(k << 5) + l];
            __stcs(&out_edge[(size_t)e * 32 + l], v);
        }
        return;
    }

    // ---- node GEMM block: 16 nodes, K=100 ----
    extern __shared__ float4 Ws[];   // [16][100]
    int nb = (bid / 5) * 3 + (m - 2);
    if (nb >= NODE_BLKS3) return;
    int base = nb * NPB3;

    for (int i = tid; i < NPB3 * ND; i += 256) {
        int t = base + i / ND;
        Ws[i] = (t < NN) ? g_Wmat[t * ND + (i % ND)] : make_float4(0.f, 0.f, 0.f, 0.f);
    }
    __syncthreads();

    int w = tid >> 5, l = tid & 31;
    const float4* Wa = &Ws[(2 * w + 0) * ND];
    const float4* Wb = &Ws[(2 * w + 1) * ND];

    float4 acc0 = make_float4(0.f, 0.f, 0.f, 0.f);
    float4 acc1 = make_float4(0.f, 0.f, 0.f, 0.f);
    float4 ss0  = make_float4(0.f, 0.f, 0.f, 0.f);   // segsum, derived
    float4 ss1  = make_float4(0.f, 0.f, 0.f, 0.f);

#pragma unroll 4
    for (int d = 0; d < ND; d++) {
        float4 wa = Wa[d], wb = Wb[d];
        if (wa.x + wb.x > 0.f) {
            float4 p = __ldg(&g_tabT[(d << 5) + l]);
            acc0.x += wa.x * p.x; acc0.y += wa.y * p.y; acc0.z += wa.z * p.z; acc0.w += wa.w * p.w;
            acc1.x += wb.x * p.x; acc1.y += wb.y * p.y; acc1.z += wb.z * p.z; acc1.w += wb.w * p.w;
            ss0.x += wa.x; ss0.y += wa.y; ss0.z += wa.z; ss0.w += wa.w;
            ss1.x += wb.x; ss1.y += wb.y; ss1.z += wb.z; ss1.w += wb.w;
        }
    }

    float gl0 = gamma[l],      bl0 = beta[l];
    float gl1 = gamma[32 + l], bl1 = beta[32 + l];
    float gl2 = gamma[64 + l], bl2 = beta[64 + l];
    float gl3 = gamma[96 + l], bl3 = beta[96 + l];

#pragma unroll
    for (int n = 0; n < 2; n++) {
        int t = base + 2 * w + n;
        if (t >= NN) break;
        float4 a  = (n == 0) ? acc0 : acc1;
        float4 ss = (n == 0) ? ss0  : ss1;
        float r0 = ss.x > 0.f ? 1.f / ss.x : 0.f;
        float r1 = ss.y > 0.f ? 1.f / ss.y : 0.f;
        float r2 = ss.z > 0.f ? 1.f / ss.z : 0.f;
        float r3 = ss.w > 0.f ? 1.f / ss.w : 0.f;
        float dg = (float)g_deg[t];
        float4 p = __ldg(&g_tabT[(nf[t] << 5) + l]);

        float v0 = a.x * r0 + dg * p.x;
        float v1 = a.y * r1 + dg * p.y;
        float v2 = a.z * r2 + dg * p.z;
        float v3 = a.w * r3 + dg * p.w;

        float s = v0 + v1 + v2 + v3;
#pragma unroll
        for (int o = 16; o; o >>= 1) s += __shfl_xor_sync(0xFFFFFFFFu, s, o);
        float mu = s * (1.f / 128.f);
        float d0 = v0 - mu, d1 = v1 - mu, d2 = v2 - mu, d3 = v3 - mu;
        float sq = d0 * d0 + d1 * d1 + d2 * d2 + d3 * d3;
#pragma unroll
        for (int o = 16; o; o >>= 1) sq += __shfl_xor_sync(0xFFFFFFFFu, sq, o);
        float rs = rsqrtf(sq * (1.f / 128.f) + 1e-5f);

        float* o0 = out_node + (size_t)t * 128;
        __stcs(&o0[l],      d0 * rs * gl0 + bl0);
        __stcs(&o0[32 + l], d1 * rs * gl1 + bl1);
        __stcs(&o0[64 + l], d2 * rs * gl2 + bl2);
        __stcs(&o0[96 + l], d3 * rs * gl3 + bl3);
    }
}

// ==================== launch ====================
extern "C" void kernel_launch(void* const* d_in, const int* in_sizes, int n_in,
                              void* d_out, int out_size) {
    const int*   nf       = (const int*)d_in[0];
    const int*   ef       = (const int*)d_in[1];
    const int*   ei       = (const int*)d_in[2];
    const float* node_emb = (const float*)d_in[3];
    const float* edge_emb = (const float*)d_in[4];
    const float* W_t      = (const float*)d_in[5];
    const float* b_t      = (const float*)d_in[6];
    const float* W_e      = (const float*)d_in[7];
    const float* b_e      = (const float*)d_in[8];
    const float* a_w      = (const float*)d_in[9];
    const float* a_b      = (const float*)d_in[10];
    const float* gamma    = (const float*)d_in[11];
    const float* beta     = (const float*)d_in[12];

    float* out_node = (float*)d_out;                                  // [25000,128]
    float4* out_edge = (float4*)((float*)d_out + (size_t)NN * 128);   // [400000,128]

    void* wmat_ptr = nullptr;
    void* deg_ptr  = nullptr;
    cudaGetSymbolAddress(&wmat_ptr, g_Wmat);
    cudaGetSymbolAddress(&deg_ptr,  g_deg);
    cudaMemsetAsync(wmat_ptr, 0, (size_t)NN * ND * sizeof(float4), 0);
    cudaMemsetAsync(deg_ptr,  0, (size_t)NN * sizeof(int), 0);

    k1_tables<<<ND + EDICT, 128>>>(node_emb, edge_emb, W_t, b_t, W_e, b_e,
                                   a_w, gamma, beta);
    k2_edges<<<K2_TOT, 256>>>(nf, ef, ei, a_b, out_edge);
    k3_nodes<<<K3_TOT, 256, SMEM3>>>(nf, ef, gamma, beta, out_node, out_edge);
}

// round 5
// speedup vs baseline: 1.7339x; 1.0804x over previous
#include <cuda_runtime.h>
#include <math.h>

#define NN 25000
#define NE 400000
#define ND 100
#define EDICT 16

// ---------------- device scratch ----------------
__device__ float4 g_tabT[ND * 32];        // P table: [d][f] -> 4 heads (51.2KB)
__device__ float4 g_s1[ND];
__device__ float4 g_s2[ND];
__device__ float4 g_s3[EDICT];
__device__ float4 g_lnedge[EDICT * 32];   // 16 LN'd edge rows (8KB)
__device__ int    g_deg[NN];
__device__ float4 g_Wmat[NN * ND];        // [t][d] -> per-head sum of exp (40MB)

// ==================== K1: fused tables + zero ====================
#define TAB_BLKS (ND + EDICT)     // 116
#define ZBLK 2048
#define K1_TOT (TAB_BLKS + ZBLK)

__global__ void __launch_bounds__(128) k1_init(
    const float* __restrict__ node_emb, const float* __restrict__ edge_emb,
    const float* __restrict__ W_t, const float* __restrict__ b_t,
    const float* __restrict__ W_e, const float* __restrict__ b_e,
    const float* __restrict__ a_w,
    const float* __restrict__ gamma, const float* __restrict__ beta)
{
    int b = blockIdx.x;
    int tid = threadIdx.x;

    if (b >= TAB_BLKS) {
        // ---- zero blocks: grid-stride over Wmat + deg ----
        int idx = (b - TAB_BLKS) * 128 + tid;
        const int stride = ZBLK * 128;
        float4 z = make_float4(0.f, 0.f, 0.f, 0.f);
        for (int i = idx; i < NN * ND; i += stride) g_Wmat[i] = z;
        for (int i = idx; i < NN; i += stride) g_deg[i] = 0;
        return;
    }

    // ---- table block: one dict row ----
    __shared__ float sh[128];
    __shared__ float red[8];
    bool isnode = (b < ND);
    const float* emb  = isnode ? (node_emb + b * 128) : (edge_emb + (b - ND) * 128);
    const float* W    = isnode ? W_t : W_e;
    const float* bias = isnode ? b_t : b_e;

    sh[tid] = emb[tid];
    __syncthreads();

    // full unroll, 2 independent chains -> deep load batching (latency fix)
    float a0 = bias[tid], a1 = 0.f;
#pragma unroll
    for (int i = 0; i < 128; i += 2) {
        a0 += sh[i]     * W[i * 128 + tid];
        a1 += sh[i + 1] * W[(i + 1) * 128 + tid];
    }
    float acc = a0 + a1;

    int h = tid >> 5;
    int f = tid & 31;

    if (isnode) {
        ((float*)&g_tabT[b * 32 + f])[h] = acc;
        float u = acc * a_w[f];
        float v = acc * a_w[32 + f];
#pragma unroll
        for (int o = 16; o; o >>= 1) {
            u += __shfl_xor_sync(0xFFFFFFFFu, u, o);
            v += __shfl_xor_sync(0xFFFFFFFFu, v, o);
        }
        if (f == 0) {
            ((float*)&g_s1[b])[h] = u;
            ((float*)&g_s2[b])[h] = v;
        }
    } else {
        int k = b - ND;
        float u = acc * a_w[64 + f];
        float s = acc;
#pragma unroll
        for (int o = 16; o; o >>= 1) {
            u += __shfl_xor_sync(0xFFFFFFFFu, u, o);
            s += __shfl_xor_sync(0xFFFFFFFFu, s, o);
        }
        if (f == 0) {
            ((float*)&g_s3[k])[h] = u;
            red[h] = s;
        }
        __syncthreads();
        float mu = (red[0] + red[1] + red[2] + red[3]) * (1.f / 128.f);
        float dd = acc - mu;
        float sq = dd * dd;
#pragma unroll
        for (int o = 16; o; o >>= 1) sq += __shfl_xor_sync(0xFFFFFFFFu, sq, o);
        if (f == 0) red[4 + h] = sq;
        __syncthreads();
        float var = (red[4] + red[5] + red[6] + red[7]) * (1.f / 128.f);
        float val = dd * rsqrtf(var + 1e-5f) * gamma[tid] + beta[tid];
        ((float*)g_lnedge)[k * 128 + tid] = val;
    }
}

// ==================== K2: edge atomics + edge-out part A ====================
#define K2_TOT 2605                 // 1042 eout + 1563 edge blocks (mod-5 interleave)
#define EO_A_BLKS 1042
#define EO_SPLIT (NE / 2)           // 200000

__global__ void __launch_bounds__(256) k2_edges(
    const int* __restrict__ nf, const int* __restrict__ ef,
    const int* __restrict__ ei, const float* __restrict__ a_b,
    float4* __restrict__ out_edge)
{
    int bid = blockIdx.x;
    int tid = threadIdx.x;
    int m = bid % 5;

    if (m < 2) {
        // ---- edge-out streaming (evict-first stores) ----
        int eb = (bid / 5) * 2 + m;
        int l = tid & 31;
        int gw = eb * 8 + (tid >> 5);
        for (int e = gw; e < EO_SPLIT; e += EO_A_BLKS * 8) {
            int k = ef[e];
            float4 v = g_lnedge[(k << 5) + l];
            __stcs(&out_edge[(size_t)e * 32 + l], v);
        }
        return;
    }

    // ---- edge logit pass ----
    int eb = (bid / 5) * 3 + (m - 2);
    int e = eb * 256 + tid;
    if (e >= NE) return;
    int s = ei[e];
    int t = ei[NE + e];
    int k = ef[e];
    int ds = nf[s];
    int dt = nf[t];
    float ab = *a_b;
    float4 z1 = g_s1[dt];
    float4 z2 = g_s2[ds];
    float4 z3 = g_s3[k];

    float zx = z1.x + z2.x + z3.x + ab;
    float zy = z1.y + z2.y + z3.y + ab;
    float zz = z1.z + z2.z + z3.z + ab;
    float zw = z1.w + z2.w + z3.w + ab;
    zx = zx >= 0.f ? zx : 0.2f * zx;
    zy = zy >= 0.f ? zy : 0.2f * zy;
    zz = zz >= 0.f ? zz : 0.2f * zz;
    zw = zw >= 0.f ? zw : 0.2f * zw;
    float ex = __expf(zx), ey = __expf(zy), ez = __expf(zz), ew = __expf(zw);

    float4* wp = &g_Wmat[t * ND + ds];
    asm volatile("red.global.add.v4.f32 [%0], {%1,%2,%3,%4};"
                 :: "l"(wp), "f"(ex), "f"(ey), "f"(ez), "f"(ew) : "memory");
    atomicAdd(&g_deg[t], 1);
}

// ==================== K3: node GEMM+LN (segsum derived) + edge-out part B ====================
#define NPB3 16
#define NODE_BLKS3 ((NN + NPB3 - 1) / NPB3)   // 1563
#define K3_TOT 2605
#define EO_B_BLKS 1042
#define SMEM3 (NPB3 * ND * sizeof(float4))    // 25.6KB

__global__ void __launch_bounds__(256) k3_nodes(
    const int* __restrict__ nf, const int* __restrict__ ef,
    const float* __restrict__ gamma, const float* __restrict__ beta,
    float* __restrict__ out_node, float4* __restrict__ out_edge)
{
    int bid = blockIdx.x;
    int tid = threadIdx.x;
    int m = bid % 5;

    if (m < 2) {
        // ---- edge-out streaming: edges [EO_SPLIT, NE) ----
        int eb = (bid / 5) * 2 + m;
        int l = tid & 31;
        int gw = eb * 8 + (tid >> 5);
        for (int e = EO_SPLIT + gw; e < NE; e += EO_B_BLKS * 8) {
            int k = ef[e];
            float4 v = g_lnedge[(k << 5) + l];
            __stcs(&out_edge[(size_t)e * 32 + l], v);
        }
        return;
    }

    // ---- node GEMM block: 16 nodes, K=100 ----
    extern __shared__ float4 Ws[];   // [16][100]
    int nb = (bid / 5) * 3 + (m - 2);
    if (nb >= NODE_BLKS3) return;
    int base = nb * NPB3;

    for (int i = tid; i < NPB3 * ND; i += 256) {
        int t = base + i / ND;
        Ws[i] = (t < NN) ? __ldcs(&g_Wmat[t * ND + (i % ND)])
                         : make_float4(0.f, 0.f, 0.f, 0.f);
    }
    __syncthreads();

    int w = tid >> 5, l = tid & 31;
    const float4* Wa = &Ws[(2 * w + 0) * ND];
    const float4* Wb = &Ws[(2 * w + 1) * ND];

    float4 acc0 = make_float4(0.f, 0.f, 0.f, 0.f);
    float4 acc1 = make_float4(0.f, 0.f, 0.f, 0.f);
    float4 ss0  = make_float4(0.f, 0.f, 0.f, 0.f);
    float4 ss1  = make_float4(0.f, 0.f, 0.f, 0.f);

#pragma unroll 4
    for (int d = 0; d < ND; d++) {
        float4 wa = Wa[d], wb = Wb[d];
        if (wa.x + wb.x > 0.f) {
            float4 p = __ldg(&g_tabT[(d << 5) + l]);
            acc0.x += wa.x * p.x; acc0.y += wa.y * p.y; acc0.z += wa.z * p.z; acc0.w += wa.w * p.w;
            acc1.x += wb.x * p.x; acc1.y += wb.y * p.y; acc1.z += wb.z * p.z; acc1.w += wb.w * p.w;
            ss0.x += wa.x; ss0.y += wa.y; ss0.z += wa.z; ss0.w += wa.w;
            ss1.x += wb.x; ss1.y += wb.y; ss1.z += wb.z; ss1.w += wb.w;
        }
    }

    float gl0 = gamma[l],      bl0 = beta[l];
    float gl1 = gamma[32 + l], bl1 = beta[32 + l];
    float gl2 = gamma[64 + l], bl2 = beta[64 + l];
    float gl3 = gamma[96 + l], bl3 = beta[96 + l];

#pragma unroll
    for (int n = 0; n < 2; n++) {
        int t = base + 2 * w + n;
        if (t >= NN) break;
        float4 a  = (n == 0) ? acc0 : acc1;
        float4 ss = (n == 0) ? ss0  : ss1;
        float r0 = ss.x > 0.f ? 1.f / ss.x : 0.f;
        float r1 = ss.y > 0.f ? 1.f / ss.y : 0.f;
        float r2 = ss.z > 0.f ? 1.f / ss.z : 0.f;
        float r3 = ss.w > 0.f ? 1.f / ss.w : 0.f;
        float dg = (float)g_deg[t];
        float4 p = __ldg(&g_tabT[(nf[t] << 5) + l]);

        float v0 = a.x * r0 + dg * p.x;
        float v1 = a.y * r1 + dg * p.y;
        float v2 = a.z * r2 + dg * p.z;
        float v3 = a.w * r3 + dg * p.w;

        float s = v0 + v1 + v2 + v3;
#pragma unroll
        for (int o = 16; o; o >>= 1) s += __shfl_xor_sync(0xFFFFFFFFu, s, o);
        float mu = s * (1.f / 128.f);
        float d0 = v0 - mu, d1 = v1 - mu, d2 = v2 - mu, d3 = v3 - mu;
        float sq = d0 * d0 + d1 * d1 + d2 * d2 + d3 * d3;
#pragma unroll
        for (int o = 16; o; o >>= 1) sq += __shfl_xor_sync(0xFFFFFFFFu, sq, o);
        float rs = rsqrtf(sq * (1.f / 128.f) + 1e-5f);

        float* o0 = out_node + (size_t)t * 128;
        __stcs(&o0[l],      d0 * rs * gl0 + bl0);
        __stcs(&o0[32 + l], d1 * rs * gl1 + bl1);
        __stcs(&o0[64 + l], d2 * rs * gl2 + bl2);
        __stcs(&o0[96 + l], d3 * rs * gl3 + bl3);
    }
}

// ==================== launch ====================
extern "C" void kernel_launch(void* const* d_in, const int* in_sizes, int n_in,
                              void* d_out, int out_size) {
    const int*   nf       = (const int*)d_in[0];
    const int*   ef       = (const int*)d_in[1];
    const int*   ei       = (const int*)d_in[2];
    const float* node_emb = (const float*)d_in[3];
    const float* edge_emb = (const float*)d_in[4];
    const float* W_t      = (const float*)d_in[5];
    const float* b_t      = (const float*)d_in[6];
    const float* W_e      = (const float*)d_in[7];
    const float* b_e      = (const float*)d_in[8];
    const float* a_w      = (const float*)d_in[9];
    const float* a_b      = (const float*)d_in[10];
    const float* gamma    = (const float*)d_in[11];
    const float* beta     = (const float*)d_in[12];

    float* out_node = (float*)d_out;                                  // [25000,128]
    float4* out_edge = (float4*)((float*)d_out + (size_t)NN * 128);   // [400000,128]

    k1_init<<<K1_TOT, 128>>>(node_emb, edge_emb, W_t, b_t, W_e, b_e,
                             a_w, gamma, beta);
    k2_edges<<<K2_TOT, 256>>>(nf, ef, ei, a_b, out_edge);
    k3_nodes<<<K3_TOT, 256, SMEM3>>>(nf, ef, gamma, beta, out_node, out_edge);
}

// round 6
// speedup vs baseline: 1.7429x; 1.0052x over previous
#include <cuda_runtime.h>
#include <math.h>

#define NN 25000
#define NE 400000
#define ND 100
#define EDICT 16

// ---------------- device scratch ----------------
__device__ float4 g_tabT[ND * 32];        // P table: [d][f] -> 4 heads (51.2KB)
__device__ float4 g_s1[ND];
__device__ float4 g_s2[ND];
__device__ float4 g_s3[EDICT];
__device__ float4 g_lnedge[EDICT * 32];   // 16 LN'd edge rows (8KB)
__device__ int    g_deg[NN];
__device__ float4 g_Wmat[NN * ND];        // [t][d] -> per-head sum of exp (40MB)

// ==================== K1: fused tables (K-split) + zero ====================
#define TAB_BLKS (ND + EDICT)     // 116
#define ZBLK 2048
#define K1_TOT (TAB_BLKS + ZBLK)

__global__ void __launch_bounds__(256) k1_init(
    const float* __restrict__ node_emb, const float* __restrict__ edge_emb,
    const float* __restrict__ W_t, const float* __restrict__ b_t,
    const float* __restrict__ W_e, const float* __restrict__ b_e,
    const float* __restrict__ a_w,
    const float* __restrict__ gamma, const float* __restrict__ beta)
{
    int b = blockIdx.x;
    int tid = threadIdx.x;

    if (b >= TAB_BLKS) {
        // ---- zero blocks: grid-stride over Wmat + deg ----
        int idx = (b - TAB_BLKS) * 256 + tid;
        const int stride = ZBLK * 256;
        float4 z = make_float4(0.f, 0.f, 0.f, 0.f);
        for (int i = idx; i < NN * ND; i += stride) g_Wmat[i] = z;
        for (int i = idx; i < NN; i += stride) g_deg[i] = 0;
        return;
    }

    // ---- table block: one dict row, K split across two 128-thread halves ----
    __shared__ float sh[128];
    __shared__ float part[128];     // partial sums from upper half
    __shared__ float red[8];
    int col = tid & 127;
    int half = tid >> 7;            // 0 or 1
    bool isnode = (b < ND);
    const float* emb  = isnode ? (node_emb + b * 128) : (edge_emb + (b - ND) * 128);
    const float* W    = isnode ? W_t : W_e;
    const float* bias = isnode ? b_t : b_e;

    if (half == 0) sh[col] = emb[col];
    __syncthreads();

    // each half sums 64 K-terms with 2 independent chains
    int k0 = half * 64;
    float a0 = 0.f, a1 = 0.f;
#pragma unroll
    for (int i = 0; i < 64; i += 2) {
        a0 += sh[k0 + i]     * W[(k0 + i) * 128 + col];
        a1 += sh[k0 + i + 1] * W[(k0 + i + 1) * 128 + col];
    }
    float partial = a0 + a1;
    if (half == 1) part[col] = partial;
    __syncthreads();
    if (half == 1) return;   // upper half done

    float acc = partial + part[col] + bias[col];

    int h = col >> 5;
    int f = col & 31;

    if (isnode) {
        ((float*)&g_tabT[b * 32 + f])[h] = acc;
        float u = acc * a_w[f];
        float v = acc * a_w[32 + f];
#pragma unroll
        for (int o = 16; o; o >>= 1) {
            u += __shfl_xor_sync(0xFFFFFFFFu, u, o);
            v += __shfl_xor_sync(0xFFFFFFFFu, v, o);
        }
        if (f == 0) {
            ((float*)&g_s1[b])[h] = u;
            ((float*)&g_s2[b])[h] = v;
        }
    } else {
        int k = b - ND;
        float u = acc * a_w[64 + f];
        float s = acc;
#pragma unroll
        for (int o = 16; o; o >>= 1) {
            u += __shfl_xor_sync(0xFFFFFFFFu, u, o);
            s += __shfl_xor_sync(0xFFFFFFFFu, s, o);
        }
        if (f == 0) {
            ((float*)&g_s3[k])[h] = u;
            red[h] = s;
        }
        __syncwarp();
        __threadfence_block();
        __syncthreads();
        float mu = (red[0] + red[1] + red[2] + red[3]) * (1.f / 128.f);
        float dd = acc - mu;
        float sq = dd * dd;
#pragma unroll
        for (int o = 16; o; o >>= 1) sq += __shfl_xor_sync(0xFFFFFFFFu, sq, o);
        if (f == 0) red[4 + h] = sq;
        __syncthreads();
        float var = (red[4] + red[5] + red[6] + red[7]) * (1.f / 128.f);
        float val = dd * rsqrtf(var + 1e-5f) * gamma[col] + beta[col];
        ((float*)g_lnedge)[k * 128 + col] = val;
    }
}

// ---------------- unrolled edge-out streamer (4-way MLP) ----------------
__device__ __forceinline__ void eout_stream(const int* __restrict__ ef,
                                            float4* __restrict__ out_edge,
                                            int start, int end, int gw, int l, int stride)
{
    int e = start + gw;
    for (; e + 3 * stride < end; e += 4 * stride) {
        int k0 = __ldg(&ef[e]);
        int k1 = __ldg(&ef[e + stride]);
        int k2 = __ldg(&ef[e + 2 * stride]);
        int k3 = __ldg(&ef[e + 3 * stride]);
        float4 v0 = g_lnedge[(k0 << 5) + l];
        float4 v1 = g_lnedge[(k1 << 5) + l];
        float4 v2 = g_lnedge[(k2 << 5) + l];
        float4 v3 = g_lnedge[(k3 << 5) + l];
        __stcs(&out_edge[(size_t)e * 32 + l], v0);
        __stcs(&out_edge[(size_t)(e + stride) * 32 + l], v1);
        __stcs(&out_edge[(size_t)(e + 2 * stride) * 32 + l], v2);
        __stcs(&out_edge[(size_t)(e + 3 * stride) * 32 + l], v3);
    }
    for (; e < end; e += stride) {
        int k = __ldg(&ef[e]);
        __stcs(&out_edge[(size_t)e * 32 + l], g_lnedge[(k << 5) + l]);
    }
}

// ==================== K2: edge atomics + edge-out part A ====================
#define K2_TOT 2605                 // 1042 eout + 1563 edge blocks (mod-5 interleave)
#define EO_A_BLKS 1042
#define EO_SPLIT (NE / 2)           // 200000

__global__ void __launch_bounds__(256) k2_edges(
    const int* __restrict__ nf, const int* __restrict__ ef,
    const int* __restrict__ ei, const float* __restrict__ a_b,
    float4* __restrict__ out_edge)
{
    int bid = blockIdx.x;
    int tid = threadIdx.x;
    int m = bid % 5;

    if (m < 2) {
        int eb = (bid / 5) * 2 + m;
        int l = tid & 31;
        int gw = eb * 8 + (tid >> 5);
        eout_stream(ef, out_edge, 0, EO_SPLIT, gw, l, EO_A_BLKS * 8);
        return;
    }

    // ---- edge logit pass ----
    int eb = (bid / 5) * 3 + (m - 2);
    int e = eb * 256 + tid;
    if (e >= NE) return;
    int s = ei[e];
    int t = ei[NE + e];
    int k = ef[e];
    int ds = nf[s];
    int dt = nf[t];
    float ab = *a_b;
    float4 z1 = g_s1[dt];
    float4 z2 = g_s2[ds];
    float4 z3 = g_s3[k];

    float zx = z1.x + z2.x + z3.x + ab;
    float zy = z1.y + z2.y + z3.y + ab;
    float zz = z1.z + z2.z + z3.z + ab;
    float zw = z1.w + z2.w + z3.w + ab;
    zx = zx >= 0.f ? zx : 0.2f * zx;
    zy = zy >= 0.f ? zy : 0.2f * zy;
    zz = zz >= 0.f ? zz : 0.2f * zz;
    zw = zw >= 0.f ? zw : 0.2f * zw;
    float ex = __expf(zx), ey = __expf(zy), ez = __expf(zz), ew = __expf(zw);

    float4* wp = &g_Wmat[t * ND + ds];
    asm volatile("red.global.add.v4.f32 [%0], {%1,%2,%3,%4};"
                 :: "l"(wp), "f"(ex), "f"(ey), "f"(ez), "f"(ew) : "memory");
    atomicAdd(&g_deg[t], 1);
}

// ==================== K3: node GEMM+LN (segsum derived) + edge-out part B ====================
#define NPB3 16
#define NODE_BLKS3 ((NN + NPB3 - 1) / NPB3)   // 1563
#define K3_TOT 2605
#define EO_B_BLKS 1042
#define SMEM3 (NPB3 * ND * sizeof(float4))    // 25.6KB

__global__ void __launch_bounds__(256) k3_nodes(
    const int* __restrict__ nf, const int* __restrict__ ef,
    const float* __restrict__ gamma, const float* __restrict__ beta,
    float* __restrict__ out_node, float4* __restrict__ out_edge)
{
    int bid = blockIdx.x;
    int tid = threadIdx.x;
    int m = bid % 5;

    if (m < 2) {
        int eb = (bid / 5) * 2 + m;
        int l = tid & 31;
        int gw = eb * 8 + (tid >> 5);
        eout_stream(ef, out_edge, EO_SPLIT, NE, gw, l, EO_B_BLKS * 8);
        return;
    }

    // ---- node GEMM block: 16 nodes, K=100 ----
    extern __shared__ float4 Ws[];   // [16][100]
    int nb = (bid / 5) * 3 + (m - 2);
    if (nb >= NODE_BLKS3) return;
    int base = nb * NPB3;

    for (int i = tid; i < NPB3 * ND; i += 256) {
        int t = base + i / ND;
        Ws[i] = (t < NN) ? __ldcs(&g_Wmat[t * ND + (i % ND)])
                         : make_float4(0.f, 0.f, 0.f, 0.f);
    }
    __syncthreads();

    int w = tid >> 5, l = tid & 31;
    const float4* Wa = &Ws[(2 * w + 0) * ND];
    const float4* Wb = &Ws[(2 * w + 1) * ND];

    float4 acc0 = make_float4(0.f, 0.f, 0.f, 0.f);
    float4 acc1 = make_float4(0.f, 0.f, 0.f, 0.f);
    float4 ss0  = make_float4(0.f, 0.f, 0.f, 0.f);
    float4 ss1  = make_float4(0.f, 0.f, 0.f, 0.f);

#pragma unroll 4
    for (int d = 0; d < ND; d++) {
        float4 wa = Wa[d], wb = Wb[d];
        if (wa.x + wb.x > 0.f) {
            float4 p = __ldg(&g_tabT[(d << 5) + l]);
            acc0.x += wa.x * p.x; acc0.y += wa.y * p.y; acc0.z += wa.z * p.z; acc0.w += wa.w * p.w;
            acc1.x += wb.x * p.x; acc1.y += wb.y * p.y; acc1.z += wb.z * p.z; acc1.w += wb.w * p.w;
            ss0.x += wa.x; ss0.y += wa.y; ss0.z += wa.z; ss0.w += wa.w;
            ss1.x += wb.x; ss1.y += wb.y; ss1.z += wb.z; ss1.w += wb.w;
        }
    }

    float gl0 = gamma[l],      bl0 = beta[l];
    float gl1 = gamma[32 + l], bl1 = beta[32 + l];
    float gl2 = gamma[64 + l], bl2 = beta[64 + l];
    float gl3 = gamma[96 + l], bl3 = beta[96 + l];

#pragma unroll
    for (int n = 0; n < 2; n++) {
        int t = base + 2 * w + n;
        if (t >= NN) break;
        float4 a  = (n == 0) ? acc0 : acc1;
        float4 ss = (n == 0) ? ss0  : ss1;
        float r0 = ss.x > 0.f ? 1.f / ss.x : 0.f;
        float r1 = ss.y > 0.f ? 1.f / ss.y : 0.f;
        float r2 = ss.z > 0.f ? 1.f / ss.z : 0.f;
        float r3 = ss.w > 0.f ? 1.f / ss.w : 0.f;
        float dg = (float)g_deg[t];
        float4 p = __ldg(&g_tabT[(nf[t] << 5) + l]);

        float v0 = a.x * r0 + dg * p.x;
        float v1 = a.y * r1 + dg * p.y;
        float v2 = a.z * r2 + dg * p.z;
        float v3 = a.w * r3 + dg * p.w;

        float s = v0 + v1 + v2 + v3;
#pragma unroll
        for (int o = 16; o; o >>= 1) s += __shfl_xor_sync(0xFFFFFFFFu, s, o);
        float mu = s * (1.f / 128.f);
        float d0 = v0 - mu, d1 = v1 - mu, d2 = v2 - mu, d3 = v3 - mu;
        float sq = d0 * d0 + d1 * d1 + d2 * d2 + d3 * d3;
#pragma unroll
        for (int o = 16; o; o >>= 1) sq += __shfl_xor_sync(0xFFFFFFFFu, sq, o);
        float rs = rsqrtf(sq * (1.f / 128.f) + 1e-5f);

        float* o0 = out_node + (size_t)t * 128;
        __stcs(&o0[l],      d0 * rs * gl0 + bl0);
        __stcs(&o0[32 + l], d1 * rs * gl1 + bl1);
        __stcs(&o0[64 + l], d2 * rs * gl2 + bl2);
        __stcs(&o0[96 + l], d3 * rs * gl3 + bl3);
    }
}

// ==================== launch ====================
extern "C" void kernel_launch(void* const* d_in, const int* in_sizes, int n_in,
                              void* d_out, int out_size) {
    const int*   nf       = (const int*)d_in[0];
    const int*   ef       = (const int*)d_in[1];
    const int*   ei       = (const int*)d_in[2];
    const float* node_emb = (const float*)d_in[3];
    const float* edge_emb = (const float*)d_in[4];
    const float* W_t      = (const float*)d_in[5];
    const float* b_t      = (const float*)d_in[6];
    const float* W_e      = (const float*)d_in[7];
    const float* b_e      = (const float*)d_in[8];
    const float* a_w      = (const float*)d_in[9];
    const float* a_b      = (const float*)d_in[10];
    const float* gamma    = (const float*)d_in[11];
    const float* beta     = (const float*)d_in[12];

    float* out_node = (float*)d_out;                                  // [25000,128]
    float4* out_edge = (float4*)((float*)d_out + (size_t)NN * 128);   // [400000,128]

    k1_init<<<K1_TOT, 256>>>(node_emb, edge_emb, W_t, b_t, W_e, b_e,
                             a_w, gamma, beta);
    k2_edges<<<K2_TOT, 256>>>(nf, ef, ei, a_b, out_edge);
    k3_nodes<<<K3_TOT, 256, SMEM3>>>(nf, ef, gamma, beta, out_node, out_edge);
}